// round 5
// baseline (speedup 1.0000x reference)
#include <cuda_runtime.h>

#define H_IN 512
#define W_IN 512
#define HW (H_IN * W_IN)
#define BC 96            // 32 batch * 3 channels
#define BC_PER_THREAD 4
#define BC_CHUNKS (BC / BC_PER_THREAD)   // 24

// max_r = log(norm(512,512)/2 * 2.0) = log(512*sqrt(2))
#define MAX_R 6.58489821531948f
#define PI_F 3.14159265358979323846f

__global__ __launch_bounds__(256) void logpolar_kernel(
    const float* __restrict__ in, float* __restrict__ out)
{
    const int pix = blockIdx.x * blockDim.x + threadIdx.x;
    const int bc0 = blockIdx.y * BC_PER_THREAD;

    const int h = pix >> 9;    // theta index (output row)
    const int w = pix & 511;   // r index (output col)

    // Match reference fp32 rounding:
    //   ang    = (2h exact) * pi (1 rnd) * 2^-9 (exact)
    //   radius = exp((w * max_r) (1 rnd) * 2^-9 (exact))
    const float ang = (float)(2 * h) * PI_F * (1.0f / 512.0f);
    const float radius = expf((float)w * MAX_R * (1.0f / 512.0f));

    float s, c;
    sincosf(ang, &s, &c);

    const float X = 256.0f + radius * c;
    const float Y = 256.0f - radius * s;

    const bool mask = (X >= 0.0f) && (X < 512.0f) && (Y >= 0.0f) && (Y < 512.0f);

    float* q = out + (size_t)bc0 * HW + pix;

    if (mask) {
        // trunc toward zero (matches .astype(int32)), then clamp
        int y_down = (int)Y; y_down = min(max(y_down, 0), H_IN - 1);
        int x_down = (int)X; x_down = min(max(x_down, 0), W_IN - 1);
        const int y_up = min(y_down + 1, H_IN - 1);
        const int x_up = min(x_down + 1, W_IN - 1);

        const float yd = Y - (float)y_down;
        const float yu = Y - (float)y_up;
        const float xd = X - (float)x_down;
        const float xu = X - (float)x_up;

        const float dd = yd * yd + xd * xd;
        const float du = yd * yd + xu * xu;
        const float ud = yu * yu + xd * xd;
        const float uu = yu * yu + xu * xu;
        const float inv_total = 1.0f / (dd + du + ud + uu);

        const float w00 = dd * inv_total;
        const float w01 = du * inv_total;
        const float w10 = ud * inv_total;
        const float w11 = uu * inv_total;

        // One aligned float4 per row covers both x-taps unless x_down%4==3
        // (and then only if not clamped at the right edge).
        const int  xb     = x_down & ~3;
        const int  idx    = x_down & 3;
        const bool hi     = (idx & 2) != 0;
        const bool lo     = (idx & 1) != 0;
        const bool need_e = (idx == 3) && (x_down != W_IN - 1);

        const int o0 = y_down * W_IN + xb;
        const int o1 = y_up   * W_IN + xb;

        const float* p = in + (size_t)bc0 * HW;

        // Batch all loads up front for MLP.
        float4 a[BC_PER_THREAD], b[BC_PER_THREAD];
        float  e0[BC_PER_THREAD], e1[BC_PER_THREAD];
        #pragma unroll
        for (int i = 0; i < BC_PER_THREAD; ++i) {
            const float* pi_ = p + (size_t)i * HW;
            a[i] = __ldg((const float4*)(pi_ + o0));
            b[i] = __ldg((const float4*)(pi_ + o1));
            if (need_e) {
                e0[i] = __ldg(pi_ + o0 + 4);
                e1[i] = __ldg(pi_ + o1 + 4);
            }
        }
        #pragma unroll
        for (int i = 0; i < BC_PER_THREAD; ++i) {
            // tap at idx
            const float v00 = hi ? (lo ? a[i].w : a[i].z) : (lo ? a[i].y : a[i].x);
            const float v10 = hi ? (lo ? b[i].w : b[i].z) : (lo ? b[i].y : b[i].x);
            // tap at idx+1 (ea/eb handle idx==3: next float4's .x, or clamped .w)
            const float ea  = need_e ? e0[i] : a[i].w;
            const float eb  = need_e ? e1[i] : b[i].w;
            const float v01 = hi ? (lo ? ea : a[i].w) : (lo ? a[i].z : a[i].y);
            const float v11 = hi ? (lo ? eb : b[i].w) : (lo ? b[i].z : b[i].y);
            q[(size_t)i * HW] = w00 * v00 + w01 * v01
                              + w10 * v10 + w11 * v11;
        }
    } else {
        #pragma unroll
        for (int i = 0; i < BC_PER_THREAD; ++i) {
            q[(size_t)i * HW] = 0.0f;
        }
    }
}

extern "C" void kernel_launch(void* const* d_in, const int* in_sizes, int n_in,
                              void* d_out, int out_size)
{
    const float* data = (const float*)d_in[0];
    float* out = (float*)d_out;
    dim3 grid(HW / 256, BC_CHUNKS);   // (1024, 24)
    logpolar_kernel<<<grid, 256>>>(data, out);
}

// round 6
// speedup vs baseline: 1.4026x; 1.4026x over previous
#include <cuda_runtime.h>

#define H_IN 512
#define W_IN 512
#define HW (H_IN * W_IN)
#define BC 96            // 32 batch * 3 channels
#define BC_PER_THREAD 4
#define BC_CHUNKS (BC / BC_PER_THREAD)   // 24

// max_r = log(norm(512,512)/2 * 2.0) = log(512*sqrt(2))
#define MAX_R 6.58489821531948f
#define PI_F 3.14159265358979323846f

// Warp covers a 4(theta) x 8(r) tile; block of 8 warps covers 8 x 32.
// Grid.x = (512/8)*(512/32) = 1024 blocks, same as before.

__global__ __launch_bounds__(256) void logpolar_kernel(
    const float* __restrict__ in, float* __restrict__ out)
{
    const int lane = threadIdx.x & 31;
    const int wp   = threadIdx.x >> 5;        // 0..7
    const int bh   = blockIdx.x >> 4;         // 0..63  (h tile)
    const int bw   = blockIdx.x & 15;         // 0..15  (w tile)

    const int h = (bh << 3) + ((wp >> 2) << 2) + (lane >> 3);  // theta row
    const int w = (bw << 5) + ((wp & 3) << 3) + (lane & 7);    // r col
    const int pix = (h << 9) + w;

    const int bc0 = blockIdx.y * BC_PER_THREAD;

    // Match reference fp32 rounding:
    //   ang    = (2h exact) * pi (1 rnd) * 2^-9 (exact)
    //   radius = exp((w * max_r) (1 rnd) * 2^-9 (exact))
    const float ang = (float)(2 * h) * PI_F * (1.0f / 512.0f);
    const float radius = expf((float)w * MAX_R * (1.0f / 512.0f));

    float s, c;
    sincosf(ang, &s, &c);

    const float X = 256.0f + radius * c;
    const float Y = 256.0f - radius * s;

    const bool mask = (X >= 0.0f) && (X < 512.0f) && (Y >= 0.0f) && (Y < 512.0f);

    float* q = out + (size_t)bc0 * HW + pix;

    if (mask) {
        // trunc toward zero (matches .astype(int32)), then clamp
        int y_down = (int)Y; y_down = min(max(y_down, 0), H_IN - 1);
        int x_down = (int)X; x_down = min(max(x_down, 0), W_IN - 1);
        const int y_up = min(y_down + 1, H_IN - 1);
        const int x_up = min(x_down + 1, W_IN - 1);

        const float yd = Y - (float)y_down;
        const float yu = Y - (float)y_up;
        const float xd = X - (float)x_down;
        const float xu = X - (float)x_up;

        const float dd = yd * yd + xd * xd;
        const float du = yd * yd + xu * xu;
        const float ud = yu * yu + xd * xd;
        const float uu = yu * yu + xu * xu;
        const float inv_total = 1.0f / (dd + du + ud + uu);

        const float w00 = dd * inv_total;
        const float w01 = du * inv_total;
        const float w10 = ud * inv_total;
        const float w11 = uu * inv_total;

        // Aligned float2 per row covers (x_down, x_down+1) when x_down even.
        const int  xb  = x_down & ~1;
        const bool odd = (x_down & 1) != 0;
        const int  o0  = y_down * W_IN + xb;     // row y_down, aligned pair
        const int  o1  = y_up   * W_IN + xb;     // row y_up,   aligned pair
        const int  oe0 = y_down * W_IN + x_up;   // extra tap when odd
        const int  oe1 = y_up   * W_IN + x_up;

        const float* p = in + (size_t)bc0 * HW;

        // Batch all loads up front for MLP.
        float2 a[BC_PER_THREAD], b[BC_PER_THREAD];
        float  e0[BC_PER_THREAD], e1[BC_PER_THREAD];
        #pragma unroll
        for (int i = 0; i < BC_PER_THREAD; ++i) {
            const float* pi_ = p + (size_t)i * HW;
            a[i] = __ldg((const float2*)(pi_ + o0));
            b[i] = __ldg((const float2*)(pi_ + o1));
            if (odd) {
                e0[i] = __ldg(pi_ + oe0);
                e1[i] = __ldg(pi_ + oe1);
            }
        }
        #pragma unroll
        for (int i = 0; i < BC_PER_THREAD; ++i) {
            const float v00 = odd ? a[i].y : a[i].x;
            const float v01 = odd ? e0[i]  : a[i].y;
            const float v10 = odd ? b[i].y : b[i].x;
            const float v11 = odd ? e1[i]  : b[i].y;
            q[(size_t)i * HW] = w00 * v00 + w01 * v01
                              + w10 * v10 + w11 * v11;
        }
    } else {
        #pragma unroll
        for (int i = 0; i < BC_PER_THREAD; ++i) {
            q[(size_t)i * HW] = 0.0f;
        }
    }
}

extern "C" void kernel_launch(void* const* d_in, const int* in_sizes, int n_in,
                              void* d_out, int out_size)
{
    const float* data = (const float*)d_in[0];
    float* out = (float*)d_out;
    dim3 grid(HW / 256, BC_CHUNKS);   // (1024, 24)
    logpolar_kernel<<<grid, 256>>>(data, out);
}

// round 7
// speedup vs baseline: 1.4954x; 1.0661x over previous
#include <cuda_runtime.h>

#define H_IN 512
#define W_IN 512
#define HW (H_IN * W_IN)
#define BC 96            // 32 batch * 3 channels
#define BC_PER_THREAD 4
#define BC_CHUNKS (BC / BC_PER_THREAD)   // 24

// max_r = log(norm(512,512)/2 * 2.0) = log(512*sqrt(2))
#define MAX_R 6.58489821531948f
#define PI_F 3.14159265358979323846f

// Warp covers a 4(theta) x 8(r) tile; block of 8 warps covers 8 x 32.
// Grid.x = (512/8)*(512/32) = 1024 blocks.

__global__ __launch_bounds__(256, 7) void logpolar_kernel(
    const float* __restrict__ in, float* __restrict__ out)
{
    const int lane = threadIdx.x & 31;
    const int wp   = threadIdx.x >> 5;        // 0..7
    const int bh   = blockIdx.x >> 4;         // 0..63  (h tile)
    const int bw   = blockIdx.x & 15;         // 0..15  (w tile)

    const int h = (bh << 3) + ((wp >> 2) << 2) + (lane >> 3);  // theta row
    const int w = (bw << 5) + ((wp & 3) << 3) + (lane & 7);    // r col
    const int pix = (h << 9) + w;

    const int bc0 = blockIdx.y * BC_PER_THREAD;

    // Match reference fp32 rounding:
    //   ang    = (2h exact) * pi (1 rnd) * 2^-9 (exact)
    //   radius = exp((w * max_r) (1 rnd) * 2^-9 (exact))
    const float ang = (float)(2 * h) * PI_F * (1.0f / 512.0f);
    const float radius = expf((float)w * MAX_R * (1.0f / 512.0f));

    float s, c;
    sincosf(ang, &s, &c);

    const float X = 256.0f + radius * c;
    const float Y = 256.0f - radius * s;

    const bool mask = (X >= 0.0f) && (X < 512.0f) && (Y >= 0.0f) && (Y < 512.0f);

    float* q = out + (size_t)bc0 * HW + pix;

    if (mask) {
        // trunc toward zero (matches .astype(int32)), then clamp
        int y_down = (int)Y; y_down = min(max(y_down, 0), H_IN - 1);
        int x_down = (int)X; x_down = min(max(x_down, 0), W_IN - 1);
        const int y_up = min(y_down + 1, H_IN - 1);
        const int x_up = min(x_down + 1, W_IN - 1);

        const float yd = Y - (float)y_down;
        const float yu = Y - (float)y_up;
        const float xd = X - (float)x_down;
        const float xu = X - (float)x_up;

        const float dd = yd * yd + xd * xd;
        const float du = yd * yd + xu * xu;
        const float ud = yu * yu + xd * xd;
        const float uu = yu * yu + xu * xu;
        const float inv_total = 1.0f / (dd + du + ud + uu);

        const float w00 = dd * inv_total;
        const float w01 = du * inv_total;
        const float w10 = ud * inv_total;
        const float w11 = uu * inv_total;

        // Aligned float2 per row covers (x_down, x_down+1) when x_down even.
        const int  xb  = x_down & ~1;
        const bool odd = (x_down & 1) != 0;
        const int  o0  = y_down * W_IN + xb;     // row y_down, aligned pair
        const int  o1  = y_up   * W_IN + xb;     // row y_up,   aligned pair
        const int  oe0 = y_down * W_IN + x_up;   // extra tap when odd
        const int  oe1 = y_up   * W_IN + x_up;

        const float* p = in + (size_t)bc0 * HW;

        // Batch loads; normalize odd lanes in place so the compute loop is
        // a straight FFMA chain on (a.x, a.y, b.x, b.y).
        float2 a[BC_PER_THREAD], b[BC_PER_THREAD];
        #pragma unroll
        for (int i = 0; i < BC_PER_THREAD; ++i) {
            const float* pi_ = p + (size_t)i * HW;
            a[i] = __ldg((const float2*)(pi_ + o0));
            b[i] = __ldg((const float2*)(pi_ + o1));
            if (odd) {
                a[i].x = a[i].y;  a[i].y = __ldg(pi_ + oe0);
                b[i].x = b[i].y;  b[i].y = __ldg(pi_ + oe1);
            }
        }
        #pragma unroll
        for (int i = 0; i < BC_PER_THREAD; ++i) {
            q[(size_t)i * HW] = w00 * a[i].x + w01 * a[i].y
                              + w10 * b[i].x + w11 * b[i].y;
        }
    } else {
        #pragma unroll
        for (int i = 0; i < BC_PER_THREAD; ++i) {
            q[(size_t)i * HW] = 0.0f;
        }
    }
}

extern "C" void kernel_launch(void* const* d_in, const int* in_sizes, int n_in,
                              void* d_out, int out_size)
{
    const float* data = (const float*)d_in[0];
    float* out = (float*)d_out;
    dim3 grid(HW / 256, BC_CHUNKS);   // (1024, 24)
    logpolar_kernel<<<grid, 256>>>(data, out);
}